// round 4
// baseline (speedup 1.0000x reference)
#include <cuda_runtime.h>

// OldNoiseConv: y[o,p] = b[o] + sum_i W[o,i] * x[i,p] * (1 + 0.1*eps[p,o,i])
// eps [32768,64,64] fp32 = 512MB read-once -> HBM-bound.
// R4: persistent CTAs (grid=592 = 4/SM exactly), grid-stride over 8-point
// groups, eps register pipeline carried ACROSS group boundaries (passes
// 13-15 of group g prefetch passes 0-2 of group g+592). W staged once.

#define P_TOT    32768
#define NCH      64
#define PPB      8
#define NGRP     (P_TOT / PPB)     // 4096 groups
#define NBLK     592               // 148 SMs * 4 CTAs
#define NTHREADS 256
#define WPAD     68

__global__ __launch_bounds__(NTHREADS, 4)
void noise_conv_kernel(const float* __restrict__ x,
                       const float* __restrict__ W,
                       const float* __restrict__ b,
                       const float* __restrict__ eps,
                       float* __restrict__ out)
{
    __shared__ float Ws[NCH][WPAD];
    __shared__ float xs[PPB][WPAD];
    __shared__ float ys[NCH][PPB + 1];
    __shared__ float bs[NCH];

    const int t  = threadIdx.x;
    const int w  = t >> 5;
    const int l  = t & 31;
    const int r4 = l >> 3;    // output row within 4-row pass group
    const int c8 = l & 7;     // float4 column within row half

    const float4* eps4 = reinterpret_cast<const float4*>(eps);

    // ---- prefetch first group's eps BEFORE anything else (DRAM busy at cycle 0)
    int g0 = blockIdx.x;
    const float4* ep = eps4 + ((size_t)(g0 * PPB + w) << 10);
    float4 A0 = __ldcs(ep + ((0 * 4 + r4) << 4) + c8);
    float4 A1 = __ldcs(ep + ((0 * 4 + r4) << 4) + 8 + c8);
    float4 B0 = __ldcs(ep + ((1 * 4 + r4) << 4) + c8);
    float4 B1 = __ldcs(ep + ((1 * 4 + r4) << 4) + 8 + c8);
    float4 C0 = __ldcs(ep + ((2 * 4 + r4) << 4) + c8);
    float4 C1 = __ldcs(ep + ((2 * 4 + r4) << 4) + 8 + c8);

    // ---- stage W once (1024 float4, 4 per thread) + bias
    {
        const float4* Wv = reinterpret_cast<const float4*>(W);
        #pragma unroll
        for (int r = 0; r < 4; r++) {
            int idx = r * NTHREADS + t;
            *reinterpret_cast<float4*>(&Ws[idx >> 4][(idx & 15) << 2]) = Wv[idx];
        }
    }
    if (t < NCH) bs[t] = b[t];

    for (int g = g0; g < NGRP; g += NBLK) {
        const int p0 = g * PPB;

        // stage x for this group (512 floats)
        #pragma unroll
        for (int r = 0; r < 2; r++) {
            int idx = r * NTHREADS + t;
            int i = idx >> 3;
            int c = idx & 7;
            xs[c][i] = x[(size_t)i * P_TOT + p0 + c];
        }
        __syncthreads();   // also orders previous flush-reads of ys before new writes

        const float4* xr  = reinterpret_cast<const float4*>(&xs[w][0]);
        const float4  xv0 = xr[c8];
        const float4  xv1 = xr[8 + c8];

        ep = eps4 + ((size_t)(p0 + w) << 10);
        const bool has_next = (g + NBLK) < NGRP;
        const float4* epn = eps4 + ((size_t)((g + NBLK) * PPB + w) << 10);

        #pragma unroll
        for (int pass = 0; pass < 16; pass++) {
            const int o = (pass << 2) + r4;

            // keep the eps stream continuous: tail passes prefetch next group
            float4 N0, N1;
            if (pass < 13) {
                const int off = (((pass + 3) << 2) + r4) << 4;
                N0 = __ldcs(ep + off + c8);
                N1 = __ldcs(ep + off + 8 + c8);
            } else if (has_next) {
                const int off = (((pass - 13) << 2) + r4) << 4;
                N0 = __ldcs(epn + off + c8);
                N1 = __ldcs(epn + off + 8 + c8);
            }

            const float4* wr = reinterpret_cast<const float4*>(&Ws[o][0]);
            const float4 w0 = wr[c8];
            const float4 w1 = wr[8 + c8];

            float s0 = (w0.x * xv0.x) * fmaf(A0.x, 0.1f, 1.0f);
            float s1 = (w0.y * xv0.y) * fmaf(A0.y, 0.1f, 1.0f);
            s0 = fmaf(w0.z * xv0.z, fmaf(A0.z, 0.1f, 1.0f), s0);
            s1 = fmaf(w0.w * xv0.w, fmaf(A0.w, 0.1f, 1.0f), s1);
            s0 = fmaf(w1.x * xv1.x, fmaf(A1.x, 0.1f, 1.0f), s0);
            s1 = fmaf(w1.y * xv1.y, fmaf(A1.y, 0.1f, 1.0f), s1);
            s0 = fmaf(w1.z * xv1.z, fmaf(A1.z, 0.1f, 1.0f), s0);
            s1 = fmaf(w1.w * xv1.w, fmaf(A1.w, 0.1f, 1.0f), s1);
            float s = s0 + s1;

            s += __shfl_xor_sync(0xffffffffu, s, 1);
            s += __shfl_xor_sync(0xffffffffu, s, 2);
            s += __shfl_xor_sync(0xffffffffu, s, 4);

            if (c8 == 0) ys[o][w] = s;

            A0 = B0; A1 = B1;
            B0 = C0; B1 = C1;
            C0 = N0; C1 = N1;
        }
        __syncthreads();   // ys writes complete

        // coalesced flush + bias (512 floats)
        #pragma unroll
        for (int r = 0; r < 2; r++) {
            int idx = r * NTHREADS + t;
            int o = idx >> 3;
            int c = idx & 7;
            out[(size_t)o * P_TOT + p0 + c] = ys[o][c] + bs[o];
        }
    }
}

extern "C" void kernel_launch(void* const* d_in, const int* in_sizes, int n_in,
                              void* d_out, int out_size)
{
    const float* x   = (const float*)d_in[0];
    const float* W   = (const float*)d_in[1];
    const float* b   = (const float*)d_in[2];
    const float* eps = (const float*)d_in[3];
    float* out = (float*)d_out;
    (void)in_sizes; (void)n_in; (void)out_size;

    noise_conv_kernel<<<NBLK, NTHREADS>>>(x, W, b, eps, out);
}

// round 5
// speedup vs baseline: 1.0607x; 1.0607x over previous
#include <cuda_runtime.h>

// OldNoiseConv: y[o,p] = b[o] + sum_i W[o,i] * x[i,p] * (1 + 0.1*eps[p,o,i])
// eps [32768,64,64] fp32 = 512MB read-once -> HBM-bound.
// R5: R3 structure (independent 8-point blocks, grid 4096, prefetch before
// staging+sync) with eps register pipeline deepened 3 -> 4 (8 front LDG.128,
// ~64 regs, still exactly 4 CTAs/SM).

#define P_TOT    32768
#define NCH      64
#define PPB      8
#define NB       (P_TOT / PPB)     // 4096
#define NTHREADS 256
#define WPAD     68

__global__ __launch_bounds__(NTHREADS, 4)
void noise_conv_kernel(const float* __restrict__ x,
                       const float* __restrict__ W,
                       const float* __restrict__ b,
                       const float* __restrict__ eps,
                       float* __restrict__ out)
{
    __shared__ float Ws[NCH][WPAD];
    __shared__ float xs[PPB][WPAD];
    __shared__ float ys[NCH][PPB + 1];
    __shared__ float bs[NCH];

    const int t  = threadIdx.x;
    const int w  = t >> 5;
    const int l  = t & 31;
    const int r4 = l >> 3;    // which of 4 output rows this pass
    const int c8 = l & 7;     // float4 column within row half
    const int p0 = blockIdx.x * PPB;
    const int p  = p0 + w;    // this warp's point

    // ---- eps prefetch FIRST (independent of smem): DRAM streams from cycle 0
    const float4* ep = reinterpret_cast<const float4*>(eps) + (size_t)p * 1024;
    float4 A0 = __ldcs(ep + ((0 * 4 + r4) << 4) + c8);
    float4 A1 = __ldcs(ep + ((0 * 4 + r4) << 4) + 8 + c8);
    float4 B0 = __ldcs(ep + ((1 * 4 + r4) << 4) + c8);
    float4 B1 = __ldcs(ep + ((1 * 4 + r4) << 4) + 8 + c8);
    float4 C0 = __ldcs(ep + ((2 * 4 + r4) << 4) + c8);
    float4 C1 = __ldcs(ep + ((2 * 4 + r4) << 4) + 8 + c8);
    float4 D0 = __ldcs(ep + ((3 * 4 + r4) << 4) + c8);
    float4 D1 = __ldcs(ep + ((3 * 4 + r4) << 4) + 8 + c8);

    // ---- stage W via float4 (1024 float4 = 4 per thread)
    {
        const float4* Wv = reinterpret_cast<const float4*>(W);
        #pragma unroll
        for (int r = 0; r < 4; r++) {
            int idx = r * NTHREADS + t;
            *reinterpret_cast<float4*>(&Ws[idx >> 4][(idx & 15) << 2]) = Wv[idx];
        }
    }
    if (t < NCH) bs[t] = b[t];

    // ---- stage x: xs[c][i] = xf[i, p0+c]  (512 floats)
    #pragma unroll
    for (int r = 0; r < 2; r++) {
        int idx = r * NTHREADS + t;
        int i = idx >> 3;
        int c = idx & 7;
        xs[c][i] = x[(size_t)i * P_TOT + p0 + c];
    }
    __syncthreads();

    const float4* xr  = reinterpret_cast<const float4*>(&xs[w][0]);
    const float4  xv0 = xr[c8];
    const float4  xv1 = xr[8 + c8];

    // ---- 16 passes, depth-4 register pipeline on eps
    #pragma unroll
    for (int pass = 0; pass < 16; pass++) {
        const int o = (pass << 2) + r4;

        float4 N0, N1;
        if (pass < 12) {
            const int off = (((pass + 4) << 2) + r4) << 4;
            N0 = __ldcs(ep + off + c8);
            N1 = __ldcs(ep + off + 8 + c8);
        }

        const float4* wr = reinterpret_cast<const float4*>(&Ws[o][0]);
        const float4 w0 = wr[c8];
        const float4 w1 = wr[8 + c8];

        float s0 = (w0.x * xv0.x) * fmaf(A0.x, 0.1f, 1.0f);
        float s1 = (w0.y * xv0.y) * fmaf(A0.y, 0.1f, 1.0f);
        s0 = fmaf(w0.z * xv0.z, fmaf(A0.z, 0.1f, 1.0f), s0);
        s1 = fmaf(w0.w * xv0.w, fmaf(A0.w, 0.1f, 1.0f), s1);
        s0 = fmaf(w1.x * xv1.x, fmaf(A1.x, 0.1f, 1.0f), s0);
        s1 = fmaf(w1.y * xv1.y, fmaf(A1.y, 0.1f, 1.0f), s1);
        s0 = fmaf(w1.z * xv1.z, fmaf(A1.z, 0.1f, 1.0f), s0);
        s1 = fmaf(w1.w * xv1.w, fmaf(A1.w, 0.1f, 1.0f), s1);
        float s = s0 + s1;

        s += __shfl_xor_sync(0xffffffffu, s, 1);
        s += __shfl_xor_sync(0xffffffffu, s, 2);
        s += __shfl_xor_sync(0xffffffffu, s, 4);

        if (c8 == 0) ys[o][w] = s;

        A0 = B0; A1 = B1;
        B0 = C0; B1 = C1;
        C0 = D0; C1 = D1;
        D0 = N0; D1 = N1;
    }
    __syncthreads();

    // ---- flush (512 floats), add bias
    #pragma unroll
    for (int r = 0; r < 2; r++) {
        int idx = r * NTHREADS + t;
        int o = idx >> 3;
        int c = idx & 7;
        out[(size_t)o * P_TOT + p0 + c] = ys[o][c] + bs[o];
    }
}

extern "C" void kernel_launch(void* const* d_in, const int* in_sizes, int n_in,
                              void* d_out, int out_size)
{
    const float* x   = (const float*)d_in[0];
    const float* W   = (const float*)d_in[1];
    const float* b   = (const float*)d_in[2];
    const float* eps = (const float*)d_in[3];
    float* out = (float*)d_out;
    (void)in_sizes; (void)n_in; (void)out_size;

    noise_conv_kernel<<<NB, NTHREADS>>>(x, W, b, eps, out);
}